// round 4
// baseline (speedup 1.0000x reference)
#include <cuda_runtime.h>
#include <cstdint>
#include <cstddef>

#define BATCH   4
#define SEQ     1024
#define DMODEL  768
#define NHEADS  12
#define HDIM    64
#define SCALE   0.125f

#define TI 16
#define TJ 64
#define RSROWS (TI + TJ - 1)
#define PAD 65

__device__ float g_q [BATCH*SEQ*DMODEL];
__device__ float g_k [BATCH*SEQ*DMODEL];
__device__ float g_v [BATCH*SEQ*DMODEL];
__device__ float g_r [2*SEQ*DMODEL];
__device__ float g_av[BATCH*SEQ*DMODEL];
__device__ float g_x [BATCH*SEQ*DMODEL];
__device__ int   g_ttflag;

__global__ void detect_tt(const unsigned int* __restrict__ p) {
    __shared__ int sI, sF;
    if (threadIdx.x == 0) { sI = 1; sF = 1; }
    __syncthreads();
    int okI = 1, okF = 1;
    for (int i = threadIdx.x; i < 4096; i += 256) {
        unsigned v = p[i];
        if (v > 1u) okI = 0;
        if (v != 0u && v != 0x3F800000u) okF = 0;
    }
    if (!okI) atomicAnd(&sI, 0);
    if (!okF) atomicAnd(&sF, 0);
    __syncthreads();
    if (threadIdx.x == 0) g_ttflag = sI ? 0 : (sF ? 1 : 2);
}

__global__ __launch_bounds__(256) void sgemm_kernel(
    const float* __restrict__ A, const float* __restrict__ B,
    const float* __restrict__ bias, const float* __restrict__ res,
    float* __restrict__ C, int M, int Nn, int K, float alpha)
{
    __shared__ float As[8][128];
    __shared__ float Bs[8][128];
    int tid = threadIdx.x;
    int tx = tid & 15, ty = tid >> 4;
    int row0 = blockIdx.y * 128, col0 = blockIdx.x * 128;
    int arow = tid >> 1, acol = (tid & 1) << 2;
    int brow = tid >> 5, bcol = (tid & 31) << 2;
    const float* Ap = A + (size_t)(row0 + arow) * K + acol;
    const float* Bp = B + (size_t)brow * Nn + col0 + bcol;
    float acc[8][8] = {};
    for (int k0 = 0; k0 < K; k0 += 8) {
        float4 av = *(const float4*)(Ap + k0);
        As[acol + 0][arow] = av.x; As[acol + 1][arow] = av.y;
        As[acol + 2][arow] = av.z; As[acol + 3][arow] = av.w;
        *(float4*)&Bs[brow][bcol] = *(const float4*)(Bp + (size_t)k0 * Nn);
        __syncthreads();
#pragma unroll
        for (int k = 0; k < 8; k++) {
            float4 a0 = *(const float4*)&As[k][ty * 8];
            float4 a1 = *(const float4*)&As[k][ty * 8 + 4];
            float4 b0 = *(const float4*)&Bs[k][tx * 8];
            float4 b1 = *(const float4*)&Bs[k][tx * 8 + 4];
            float a[8] = {a0.x, a0.y, a0.z, a0.w, a1.x, a1.y, a1.z, a1.w};
            float b[8] = {b0.x, b0.y, b0.z, b0.w, b1.x, b1.y, b1.z, b1.w};
#pragma unroll
            for (int ii = 0; ii < 8; ii++)
#pragma unroll
                for (int jj = 0; jj < 8; jj++)
                    acc[ii][jj] += a[ii] * b[jj];
        }
        __syncthreads();
    }
#pragma unroll
    for (int ii = 0; ii < 8; ii++) {
        int r = row0 + ty * 8 + ii;
#pragma unroll
        for (int jj = 0; jj < 8; jj += 4) {
            int c = col0 + tx * 8 + jj;
            float4 o;
            o.x = alpha * acc[ii][jj + 0];
            o.y = alpha * acc[ii][jj + 1];
            o.z = alpha * acc[ii][jj + 2];
            o.w = alpha * acc[ii][jj + 3];
            if (bias) { o.x += bias[c]; o.y += bias[c + 1]; o.z += bias[c + 2]; o.w += bias[c + 3]; }
            if (res) {
                const float* rp = res + (size_t)r * Nn + c;
                o.x += rp[0]; o.y += rp[1]; o.z += rp[2]; o.w += rp[3];
            }
            *(float4*)&C[(size_t)r * Nn + c] = o;
        }
    }
}

// Fused relative attention. Q kept in registers; score dot products use
// shuffle-broadcast of q so each FMA has at most one shared-memory operand.
__global__ __launch_bounds__(512) void attn_kernel(
    const float* __restrict__ qh, const float* __restrict__ kh,
    const float* __restrict__ vh, const float* __restrict__ rh,
    const void*  __restrict__ ttp,
    const float* __restrict__ amask, const float* __restrict__ clsm,
    const float* __restrict__ rwb, const float* __restrict__ rrb,
    const float* __restrict__ rsb, const float* __restrict__ seg,
    float* __restrict__ av)
{
    extern __shared__ float sm[];
    float* Ks = sm;                 // TJ*PAD
    float* Vs = Ks + TJ * PAD;      // TJ*PAD
    float* Rs = Vs + TJ * PAD;      // RSROWS*PAD

    int tid = threadIdx.x;
    int w = tid >> 5, lane = tid & 31;
    int i0 = blockIdx.x * TI;
    int b = blockIdx.y / NHEADS, n = blockIdx.y % NHEADS;
    int i = i0 + w;
    int nh = n * HDIM;
    int flag = g_ttflag;

    // per-row query variants in registers (lane holds dims lane, lane+32)
    const float* qrow = qh + ((size_t)(b * SEQ + i)) * DMODEL + nh;
    float q0 = qrow[lane], q1 = qrow[lane + 32];
    float qw0 = q0 + __ldg(&rwb[nh + lane]) * SCALE;
    float qw1 = q1 + __ldg(&rwb[nh + lane + 32]) * SCALE;
    float qr0 = q0 + __ldg(&rrb[nh + lane]) * SCALE;
    float qr1 = q1 + __ldg(&rrb[nh + lane + 32]) * SCALE;
    float qs0 = q0 + __ldg(&rsb[nh + lane]) * SCALE;
    float qs1 = q1 + __ldg(&rsb[nh + lane + 32]) * SCALE;
    float td = qs0 * __ldg(&seg[nh + lane]) + qs1 * __ldg(&seg[nh + lane + 32]);
    float ts = qs0 * __ldg(&seg[DMODEL + nh + lane]) + qs1 * __ldg(&seg[DMODEL + nh + lane + 32]);
#pragma unroll
    for (int o = 16; o; o >>= 1) {
        td += __shfl_xor_sync(0xffffffffu, td, o);
        ts += __shfl_xor_sync(0xffffffffu, ts, o);
    }

    float mrun = -1e30f, lrun = 0.f, acc0 = 0.f, acc1 = 0.f;
    const unsigned char* tt8  = (const unsigned char*)ttp;
    const int*           tt32 = (const int*)ttp;
    const float*         ttf  = (const float*)ttp;

    for (int jt = 0; jt < SEQ / TJ; jt++) {
        int j0 = jt * TJ;
#pragma unroll
        for (int l = 0; l < 2; l++) {
            int idx = tid + l * 512;
            int rrow = idx >> 4, c4 = (idx & 15) << 2;
            size_t gsrc = ((size_t)(b * SEQ + j0 + rrow)) * DMODEL + nh + c4;
            float4 kv = *(const float4*)&kh[gsrc];
            float4 vv = *(const float4*)&vh[gsrc];
            float* kd = &Ks[rrow * PAD + c4];
            kd[0] = kv.x; kd[1] = kv.y; kd[2] = kv.z; kd[3] = kv.w;
            float* vd = &Vs[rrow * PAD + c4];
            vd[0] = vv.x; vd[1] = vv.y; vd[2] = vv.z; vd[3] = vv.w;
        }
        int tb = SEQ + j0 - i0 - (TI - 1);
#pragma unroll
        for (int l = 0; l < 3; l++) {
            int idx = tid + l * 512;
            if (idx < RSROWS * 16) {
                int rrow = idx >> 4, c4 = (idx & 15) << 2;
                float4 rv = *(const float4*)&rh[((size_t)(tb + rrow)) * DMODEL + nh + c4];
                float* rd = &Rs[rrow * PAD + c4];
                rd[0] = rv.x; rd[1] = rv.y; rd[2] = rv.z; rd[3] = rv.w;
            }
        }
        __syncthreads();

        int c0 = lane, c1 = lane + 32;
        const float* kp0 = &Ks[c0 * PAD];
        const float* kp1 = &Ks[c1 * PAD];
        const float* rp0 = &Rs[(c0 - w + TI - 1) * PAD];
        const float* rp1 = &Rs[(c1 - w + TI - 1) * PAD];
        float s0 = 0.f, s1 = 0.f, p0 = 0.f, p1 = 0.f;
#pragma unroll
        for (int h = 0; h < 32; h++) {
            float qa = __shfl_sync(0xffffffffu, qw0, h);
            float qb = __shfl_sync(0xffffffffu, qr0, h);
            s0 += qa * kp0[h]; s1 += qa * kp1[h];
            p0 += qb * rp0[h]; p1 += qb * rp1[h];
        }
#pragma unroll
        for (int h = 0; h < 32; h++) {
            float qa = __shfl_sync(0xffffffffu, qw1, h);
            float qb = __shfl_sync(0xffffffffu, qr1, h);
            s0 += qa * kp0[h + 32]; s1 += qa * kp1[h + 32];
            p0 += qb * rp0[h + 32]; p1 += qb * rp1[h + 32];
        }
        size_t cbase = (size_t)i * SEQ + j0;
        float cls0 = __ldg(&clsm[cbase + c0]);
        float cls1 = __ldg(&clsm[cbase + c1]);
        size_t tbase = ((size_t)b * SEQ + i) * SEQ + j0;
        bool m0, m1;
        if (flag == 2)      { m0 = tt8 [tbase + c0] != 0;   m1 = tt8 [tbase + c1] != 0; }
        else if (flag == 0) { m0 = tt32[tbase + c0] != 0;   m1 = tt32[tbase + c1] != 0; }
        else                { m0 = ttf [tbase + c0] != 0.f; m1 = ttf [tbase + c1] != 0.f; }
        float tt0 = m0 ? ts : td, tt1 = m1 ? ts : td;
        float am0 = __ldg(&amask[b * SEQ + j0 + c0]);
        float am1 = __ldg(&amask[b * SEQ + j0 + c1]);
        float sc0 = s0 + (p0 + tt0) * cls0 - 1000000.0f * (1.f - am0);
        float sc1 = s1 + (p1 + tt1) * cls1 - 1000000.0f * (1.f - am1);

        float mloc = fmaxf(sc0, sc1);
#pragma unroll
        for (int o = 16; o; o >>= 1) mloc = fmaxf(mloc, __shfl_xor_sync(0xffffffffu, mloc, o));
        float mnew = fmaxf(mrun, mloc);
        float corr = __expf(mrun - mnew);
        float e0 = __expf(sc0 - mnew), e1 = __expf(sc1 - mnew);
        float ls = e0 + e1;
#pragma unroll
        for (int o = 16; o; o >>= 1) ls += __shfl_xor_sync(0xffffffffu, ls, o);
        lrun = lrun * corr + ls;
        mrun = mnew;
        acc0 *= corr; acc1 *= corr;
        // PV via shuffle-broadcast of probabilities (no smem P staging)
#pragma unroll
        for (int j = 0; j < 32; j++) {
            float e = __shfl_sync(0xffffffffu, e0, j);
            acc0 += e * Vs[j * PAD + lane];
            acc1 += e * Vs[j * PAD + lane + 32];
        }
#pragma unroll
        for (int j = 0; j < 32; j++) {
            float e = __shfl_sync(0xffffffffu, e1, j);
            acc0 += e * Vs[(j + 32) * PAD + lane];
            acc1 += e * Vs[(j + 32) * PAD + lane + 32];
        }
        __syncthreads();
    }
    float inv = 1.f / lrun;
    float* od = av + ((size_t)(b * SEQ + i)) * DMODEL + nh;
    od[lane]      = acc0 * inv;
    od[lane + 32] = acc1 * inv;
}

__global__ __launch_bounds__(256) void ln_kernel(
    const float* __restrict__ x, const float* __restrict__ g,
    const float* __restrict__ bta, float* __restrict__ out)
{
    int row = blockIdx.x;
    int t = threadIdx.x;
    const float* xr = x + (size_t)row * DMODEL;
    float v0 = xr[t], v1 = xr[t + 256], v2 = xr[t + 512];
    __shared__ float red[32];
    int w = t >> 5, lane = t & 31;
    float s = v0 + v1 + v2;
#pragma unroll
    for (int o = 16; o; o >>= 1) s += __shfl_xor_sync(0xffffffffu, s, o);
    if (lane == 0) red[w] = s;
    __syncthreads();
    if (t < 32) {
        float r = (t < 8) ? red[t] : 0.f;
#pragma unroll
        for (int o = 4; o; o >>= 1) r += __shfl_xor_sync(0xffffffffu, r, o);
        if (t == 0) red[0] = r;
    }
    __syncthreads();
    float mu = red[0] * (1.f / DMODEL);
    float d0 = v0 - mu, d1 = v1 - mu, d2 = v2 - mu;
    float qv = d0 * d0 + d1 * d1 + d2 * d2;
#pragma unroll
    for (int o = 16; o; o >>= 1) qv += __shfl_xor_sync(0xffffffffu, qv, o);
    __syncthreads();
    if (lane == 0) red[w] = qv;
    __syncthreads();
    if (t < 32) {
        float r = (t < 8) ? red[t] : 0.f;
#pragma unroll
        for (int o = 4; o; o >>= 1) r += __shfl_xor_sync(0xffffffffu, r, o);
        if (t == 0) red[0] = r;
    }
    __syncthreads();
    float var = red[0] * (1.f / DMODEL);
    float rstd = rsqrtf(var + 1e-9f);
    size_t ob = (size_t)row * DMODEL;
    out[ob + t]       = d0 * rstd * g[t]       + bta[t];
    out[ob + t + 256] = d1 * rstd * g[t + 256] + bta[t + 256];
    out[ob + t + 512] = d2 * rstd * g[t + 512] + bta[t + 512];
}

static const int ATTN_SMEM = (2 * TJ * PAD + RSROWS * PAD) * (int)sizeof(float);

extern "C" void kernel_launch(void* const* d_in, const int* in_sizes, int n_in,
                              void* d_out, int out_size)
{
    (void)in_sizes; (void)n_in; (void)out_size;
    const float* query = (const float*)d_in[0];
    const float* key   = (const float*)d_in[1];
    const float* value = (const float*)d_in[2];
    const float* pos   = (const float*)d_in[3];
    const void*  ttm   = d_in[4];
    const float* amask = (const float*)d_in[5];
    const float* clsm  = (const float*)d_in[6];
    const float* Wq    = (const float*)d_in[7];
    const float* Wk    = (const float*)d_in[8];
    const float* bk    = (const float*)d_in[9];
    const float* Wv    = (const float*)d_in[10];
    const float* bv    = (const float*)d_in[11];
    const float* rwb   = (const float*)d_in[12];
    const float* rrb   = (const float*)d_in[13];
    const float* rker  = (const float*)d_in[14];
    const float* rsb   = (const float*)d_in[15];
    const float* seg   = (const float*)d_in[16];
    const float* Wo    = (const float*)d_in[17];
    const float* bo    = (const float*)d_in[18];
    const float* lng   = (const float*)d_in[19];
    const float* lnb   = (const float*)d_in[20];

    float *gq, *gk, *gv, *gr, *gav, *gx;
    cudaGetSymbolAddress((void**)&gq,  g_q);
    cudaGetSymbolAddress((void**)&gk,  g_k);
    cudaGetSymbolAddress((void**)&gv,  g_v);
    cudaGetSymbolAddress((void**)&gr,  g_r);
    cudaGetSymbolAddress((void**)&gav, g_av);
    cudaGetSymbolAddress((void**)&gx,  g_x);

    cudaFuncSetAttribute(attn_kernel, cudaFuncAttributeMaxDynamicSharedMemorySize, ATTN_SMEM);

    detect_tt<<<1, 256>>>((const unsigned int*)ttm);

    sgemm_kernel<<<dim3(6, 32), 256>>>(query, Wq, nullptr, nullptr, gq,
                                       BATCH * SEQ, DMODEL, DMODEL, SCALE);
    sgemm_kernel<<<dim3(6, 32), 256>>>(key, Wk, bk, nullptr, gk,
                                       BATCH * SEQ, DMODEL, DMODEL, 1.f);
    sgemm_kernel<<<dim3(6, 32), 256>>>(value, Wv, bv, nullptr, gv,
                                       BATCH * SEQ, DMODEL, DMODEL, 1.f);
    sgemm_kernel<<<dim3(6, 16), 256>>>(pos, rker, nullptr, nullptr, gr,
                                       2 * SEQ, DMODEL, DMODEL, 1.f);

    attn_kernel<<<dim3(SEQ / TI, BATCH * NHEADS), 512, ATTN_SMEM>>>(
        gq, gk, gv, gr, ttm, amask, clsm, rwb, rrb, rsb, seg, gav);

    sgemm_kernel<<<dim3(6, 32), 256>>>(gav, Wo, bo, query, gx,
                                       BATCH * SEQ, DMODEL, DMODEL, 1.f);

    ln_kernel<<<BATCH * SEQ, 256>>>(gx, lng, lnb, (float*)d_out);
}

// round 5
// speedup vs baseline: 1.3254x; 1.3254x over previous
#include <cuda_runtime.h>
#include <cstdint>
#include <cstddef>

#define BATCH   4
#define SEQ     1024
#define DMODEL  768
#define NHEADS  12
#define HDIM    64
#define SCALE   0.125f

#define TI 16
#define TJ 64
#define RSROWS (TI + TJ - 1)
#define PAD 65

// tf32 GEMM tiles
#define GBM 128
#define GBN 128
#define GBK 32
#define ASTRIDE 36
#define BSTRIDE 132

__device__ float g_q [BATCH*SEQ*DMODEL];
__device__ float g_k [BATCH*SEQ*DMODEL];
__device__ float g_v [BATCH*SEQ*DMODEL];
__device__ float g_r [2*SEQ*DMODEL];
__device__ float g_av[BATCH*SEQ*DMODEL];
__device__ float g_x [BATCH*SEQ*DMODEL];
__device__ int   g_ttflag;

__global__ void detect_tt(const unsigned int* __restrict__ p) {
    __shared__ int sI, sF;
    if (threadIdx.x == 0) { sI = 1; sF = 1; }
    __syncthreads();
    int okI = 1, okF = 1;
    for (int i = threadIdx.x; i < 4096; i += 256) {
        unsigned v = p[i];
        if (v > 1u) okI = 0;
        if (v != 0u && v != 0x3F800000u) okF = 0;
    }
    if (!okI) atomicAnd(&sI, 0);
    if (!okF) atomicAnd(&sF, 0);
    __syncthreads();
    if (threadIdx.x == 0) g_ttflag = sI ? 0 : (sF ? 1 : 2);
}

__device__ __forceinline__ uint32_t f2tf32(float x) {
    uint32_t r;
    asm("cvt.rna.tf32.f32 %0, %1;" : "=r"(r) : "f"(x));
    return r;
}

__device__ __forceinline__ void mma_tf32(float* c, const uint32_t* a, const uint32_t* b) {
    asm volatile(
        "mma.sync.aligned.m16n8k8.row.col.f32.tf32.tf32.f32 "
        "{%0,%1,%2,%3}, {%4,%5,%6,%7}, {%8,%9}, {%0,%1,%2,%3};"
        : "+f"(c[0]), "+f"(c[1]), "+f"(c[2]), "+f"(c[3])
        : "r"(a[0]), "r"(a[1]), "r"(a[2]), "r"(a[3]), "r"(b[0]), "r"(b[1]));
}

// C = alpha*(A@B) (+bias) (+res), tf32 tensor-core path.
// A: MxK row-major, B: KxN row-major. M%128==0, N%128==0, K%32==0.
__global__ __launch_bounds__(256) void tgemm_kernel(
    const float* __restrict__ A, const float* __restrict__ B,
    const float* __restrict__ bias, const float* __restrict__ res,
    float* __restrict__ C, int M, int Nn, int K, float alpha)
{
    __shared__ uint32_t As[GBM][ASTRIDE];   // 128 x 36
    __shared__ uint32_t Bs[GBK][BSTRIDE];   // 32 x 132
    int tid = threadIdx.x;
    int warp = tid >> 5, lane = tid & 31;
    int wm = warp >> 2, wn = warp & 3;       // warps 2 (M) x 4 (N)
    int gid = lane >> 2, tig = lane & 3;     // groupID, thread-in-group
    int row0 = blockIdx.y * GBM, col0 = blockIdx.x * GBN;

    float acc[4][4][4];
#pragma unroll
    for (int mt = 0; mt < 4; mt++)
#pragma unroll
        for (int nt = 0; nt < 4; nt++)
#pragma unroll
            for (int e = 0; e < 4; e++) acc[mt][nt][e] = 0.f;

    for (int k0 = 0; k0 < K; k0 += GBK) {
        // stage A 128x32 and B 32x128 (1024 float4 each; 4 per thread each)
#pragma unroll
        for (int l = 0; l < 4; l++) {
            int idx = l * 256 + tid;
            int ra = idx >> 3, ca = (idx & 7) << 2;
            float4 va = *(const float4*)&A[(size_t)(row0 + ra) * K + k0 + ca];
            As[ra][ca + 0] = f2tf32(va.x);
            As[ra][ca + 1] = f2tf32(va.y);
            As[ra][ca + 2] = f2tf32(va.z);
            As[ra][ca + 3] = f2tf32(va.w);
            int rb = idx >> 5, cb = (idx & 31) << 2;
            float4 vb = *(const float4*)&B[(size_t)(k0 + rb) * Nn + col0 + cb];
            Bs[rb][cb + 0] = f2tf32(vb.x);
            Bs[rb][cb + 1] = f2tf32(vb.y);
            Bs[rb][cb + 2] = f2tf32(vb.z);
            Bs[rb][cb + 3] = f2tf32(vb.w);
        }
        __syncthreads();
#pragma unroll
        for (int kk = 0; kk < GBK; kk += 8) {
            uint32_t af[4][4];
#pragma unroll
            for (int mt = 0; mt < 4; mt++) {
                int r = wm * 64 + mt * 16 + gid;
                af[mt][0] = As[r    ][kk + tig];
                af[mt][1] = As[r + 8][kk + tig];
                af[mt][2] = As[r    ][kk + tig + 4];
                af[mt][3] = As[r + 8][kk + tig + 4];
            }
            uint32_t bf[4][2];
#pragma unroll
            for (int nt = 0; nt < 4; nt++) {
                int cn = wn * 32 + nt * 8 + gid;
                bf[nt][0] = Bs[kk + tig    ][cn];
                bf[nt][1] = Bs[kk + tig + 4][cn];
            }
#pragma unroll
            for (int mt = 0; mt < 4; mt++)
#pragma unroll
                for (int nt = 0; nt < 4; nt++)
                    mma_tf32(acc[mt][nt], af[mt], bf[nt]);
        }
        __syncthreads();
    }

    // epilogue
#pragma unroll
    for (int mt = 0; mt < 4; mt++) {
        int r = row0 + wm * 64 + mt * 16 + gid;
#pragma unroll
        for (int nt = 0; nt < 4; nt++) {
            int cn = col0 + wn * 32 + nt * 8 + tig * 2;
            float2 o0, o1;
            o0.x = alpha * acc[mt][nt][0]; o0.y = alpha * acc[mt][nt][1];
            o1.x = alpha * acc[mt][nt][2]; o1.y = alpha * acc[mt][nt][3];
            if (bias) {
                o0.x += bias[cn]; o0.y += bias[cn + 1];
                o1.x += bias[cn]; o1.y += bias[cn + 1];
            }
            if (res) {
                const float* rp0 = res + (size_t)r * Nn + cn;
                const float* rp1 = res + (size_t)(r + 8) * Nn + cn;
                o0.x += rp0[0]; o0.y += rp0[1];
                o1.x += rp1[0]; o1.y += rp1[1];
            }
            *(float2*)&C[(size_t)r * Nn + cn] = o0;
            *(float2*)&C[(size_t)(r + 8) * Nn + cn] = o1;
        }
    }
}

// Fused relative attention (R1-proven version: smem Q variants + smem P staging).
__global__ __launch_bounds__(512) void attn_kernel(
    const float* __restrict__ qh, const float* __restrict__ kh,
    const float* __restrict__ vh, const float* __restrict__ rh,
    const void*  __restrict__ ttp,
    const float* __restrict__ amask, const float* __restrict__ clsm,
    const float* __restrict__ rwb, const float* __restrict__ rrb,
    const float* __restrict__ rsb, const float* __restrict__ seg,
    float* __restrict__ av)
{
    extern __shared__ float sm[];
    float* Ks = sm;                       // TJ*PAD
    float* Vs = Ks + TJ * PAD;            // TJ*PAD
    float* Rs = Vs + TJ * PAD;            // RSROWS*PAD
    float* Qw = Rs + RSROWS * PAD;        // TI*PAD
    float* Qr = Qw + TI * PAD;            // TI*PAD
    float* Ps = Qr + TI * PAD;            // TI*TJ

    int tid = threadIdx.x;
    int w = tid >> 5, lane = tid & 31;
    int i0 = blockIdx.x * TI;
    int b = blockIdx.y / NHEADS, n = blockIdx.y % NHEADS;
    int i = i0 + w;
    int nh = n * HDIM;
    int flag = g_ttflag;

    const float* qrow = qh + ((size_t)(b * SEQ + i)) * DMODEL + nh;
    float q0 = qrow[lane], q1 = qrow[lane + 32];
    Qw[w * PAD + lane]      = q0 + __ldg(&rwb[nh + lane]) * SCALE;
    Qw[w * PAD + lane + 32] = q1 + __ldg(&rwb[nh + lane + 32]) * SCALE;
    Qr[w * PAD + lane]      = q0 + __ldg(&rrb[nh + lane]) * SCALE;
    Qr[w * PAD + lane + 32] = q1 + __ldg(&rrb[nh + lane + 32]) * SCALE;
    float qs0 = q0 + __ldg(&rsb[nh + lane]) * SCALE;
    float qs1 = q1 + __ldg(&rsb[nh + lane + 32]) * SCALE;
    float td = qs0 * __ldg(&seg[nh + lane]) + qs1 * __ldg(&seg[nh + lane + 32]);
    float ts = qs0 * __ldg(&seg[DMODEL + nh + lane]) + qs1 * __ldg(&seg[DMODEL + nh + lane + 32]);
#pragma unroll
    for (int o = 16; o; o >>= 1) {
        td += __shfl_xor_sync(0xffffffffu, td, o);
        ts += __shfl_xor_sync(0xffffffffu, ts, o);
    }

    float mrun = -1e30f, lrun = 0.f, acc0 = 0.f, acc1 = 0.f;
    const unsigned char* tt8  = (const unsigned char*)ttp;
    const int*           tt32 = (const int*)ttp;
    const float*         ttf  = (const float*)ttp;

    for (int jt = 0; jt < SEQ / TJ; jt++) {
        int j0 = jt * TJ;
#pragma unroll
        for (int l = 0; l < 2; l++) {
            int idx = tid + l * 512;
            int rrow = idx >> 4, c4 = (idx & 15) << 2;
            size_t gsrc = ((size_t)(b * SEQ + j0 + rrow)) * DMODEL + nh + c4;
            float4 kv = *(const float4*)&kh[gsrc];
            float4 vv = *(const float4*)&vh[gsrc];
            float* kd = &Ks[rrow * PAD + c4];
            kd[0] = kv.x; kd[1] = kv.y; kd[2] = kv.z; kd[3] = kv.w;
            float* vd = &Vs[rrow * PAD + c4];
            vd[0] = vv.x; vd[1] = vv.y; vd[2] = vv.z; vd[3] = vv.w;
        }
        int tb = SEQ + j0 - i0 - (TI - 1);
#pragma unroll
        for (int l = 0; l < 3; l++) {
            int idx = tid + l * 512;
            if (idx < RSROWS * 16) {
                int rrow = idx >> 4, c4 = (idx & 15) << 2;
                float4 rv = *(const float4*)&rh[((size_t)(tb + rrow)) * DMODEL + nh + c4];
                float* rd = &Rs[rrow * PAD + c4];
                rd[0] = rv.x; rd[1] = rv.y; rd[2] = rv.z; rd[3] = rv.w;
            }
        }
        __syncthreads();

        int c0 = lane, c1 = lane + 32;
        const float* kp0 = &Ks[c0 * PAD];
        const float* kp1 = &Ks[c1 * PAD];
        const float* rp0 = &Rs[(c0 - w + TI - 1) * PAD];
        const float* rp1 = &Rs[(c1 - w + TI - 1) * PAD];
        const float* qwp = &Qw[w * PAD];
        const float* qrp = &Qr[w * PAD];
        float s0 = 0.f, s1 = 0.f, p0 = 0.f, p1 = 0.f;
#pragma unroll
        for (int h = 0; h < HDIM; h++) {
            float qa = qwp[h], qb = qrp[h];
            s0 += qa * kp0[h]; s1 += qa * kp1[h];
            p0 += qb * rp0[h]; p1 += qb * rp1[h];
        }
        size_t cbase = (size_t)i * SEQ + j0;
        float cls0 = __ldg(&clsm[cbase + c0]);
        float cls1 = __ldg(&clsm[cbase + c1]);
        size_t tbase = ((size_t)b * SEQ + i) * SEQ + j0;
        bool m0, m1;
        if (flag == 2)      { m0 = tt8 [tbase + c0] != 0;   m1 = tt8 [tbase + c1] != 0; }
        else if (flag == 0) { m0 = tt32[tbase + c0] != 0;   m1 = tt32[tbase + c1] != 0; }
        else                { m0 = ttf [tbase + c0] != 0.f; m1 = ttf [tbase + c1] != 0.f; }
        float tt0 = m0 ? ts : td, tt1 = m1 ? ts : td;
        float am0 = __ldg(&amask[b * SEQ + j0 + c0]);
        float am1 = __ldg(&amask[b * SEQ + j0 + c1]);
        float sc0 = s0 + (p0 + tt0) * cls0 - 1000000.0f * (1.f - am0);
        float sc1 = s1 + (p1 + tt1) * cls1 - 1000000.0f * (1.f - am1);

        float mloc = fmaxf(sc0, sc1);
#pragma unroll
        for (int o = 16; o; o >>= 1) mloc = fmaxf(mloc, __shfl_xor_sync(0xffffffffu, mloc, o));
        float mnew = fmaxf(mrun, mloc);
        float corr = __expf(mrun - mnew);
        float e0 = __expf(sc0 - mnew), e1 = __expf(sc1 - mnew);
        float ls = e0 + e1;
#pragma unroll
        for (int o = 16; o; o >>= 1) ls += __shfl_xor_sync(0xffffffffu, ls, o);
        lrun = lrun * corr + ls;
        mrun = mnew;
        acc0 *= corr; acc1 *= corr;
        Ps[w * TJ + c0] = e0; Ps[w * TJ + c1] = e1;
        __syncwarp();
#pragma unroll 8
        for (int j = 0; j < TJ; j++) {
            float e = Ps[w * TJ + j];
            acc0 += e * Vs[j * PAD + lane];
            acc1 += e * Vs[j * PAD + lane + 32];
        }
        __syncthreads();
    }
    float inv = 1.f / lrun;
    float* od = av + ((size_t)(b * SEQ + i)) * DMODEL + nh;
    od[lane]      = acc0 * inv;
    od[lane + 32] = acc1 * inv;
}

__global__ __launch_bounds__(256) void ln_kernel(
    const float* __restrict__ x, const float* __restrict__ g,
    const float* __restrict__ bta, float* __restrict__ out)
{
    int row = blockIdx.x;
    int t = threadIdx.x;
    const float* xr = x + (size_t)row * DMODEL;
    float v0 = xr[t], v1 = xr[t + 256], v2 = xr[t + 512];
    __shared__ float red[32];
    int w = t >> 5, lane = t & 31;
    float s = v0 + v1 + v2;
#pragma unroll
    for (int o = 16; o; o >>= 1) s += __shfl_xor_sync(0xffffffffu, s, o);
    if (lane == 0) red[w] = s;
    __syncthreads();
    if (t < 32) {
        float r = (t < 8) ? red[t] : 0.f;
#pragma unroll
        for (int o = 4; o; o >>= 1) r += __shfl_xor_sync(0xffffffffu, r, o);
        if (t == 0) red[0] = r;
    }
    __syncthreads();
    float mu = red[0] * (1.f / DMODEL);
    float d0 = v0 - mu, d1 = v1 - mu, d2 = v2 - mu;
    float qv = d0 * d0 + d1 * d1 + d2 * d2;
#pragma unroll
    for (int o = 16; o; o >>= 1) qv += __shfl_xor_sync(0xffffffffu, qv, o);
    __syncthreads();
    if (lane == 0) red[w] = qv;
    __syncthreads();
    if (t < 32) {
        float r = (t < 8) ? red[t] : 0.f;
#pragma unroll
        for (int o = 4; o; o >>= 1) r += __shfl_xor_sync(0xffffffffu, r, o);
        if (t == 0) red[0] = r;
    }
    __syncthreads();
    float var = red[0] * (1.f / DMODEL);
    float rstd = rsqrtf(var + 1e-9f);
    size_t ob = (size_t)row * DMODEL;
    out[ob + t]       = d0 * rstd * g[t]       + bta[t];
    out[ob + t + 256] = d1 * rstd * g[t + 256] + bta[t + 256];
    out[ob + t + 512] = d2 * rstd * g[t + 512] + bta[t + 512];
}

static const int ATTN_SMEM = (2 * TJ * PAD + RSROWS * PAD + 2 * TI * PAD + TI * TJ) * (int)sizeof(float);

extern "C" void kernel_launch(void* const* d_in, const int* in_sizes, int n_in,
                              void* d_out, int out_size)
{
    (void)in_sizes; (void)n_in; (void)out_size;
    const float* query = (const float*)d_in[0];
    const float* key   = (const float*)d_in[1];
    const float* value = (const float*)d_in[2];
    const float* pos   = (const float*)d_in[3];
    const void*  ttm   = d_in[4];
    const float* amask = (const float*)d_in[5];
    const float* clsm  = (const float*)d_in[6];
    const float* Wq    = (const float*)d_in[7];
    const float* Wk    = (const float*)d_in[8];
    const float* bk    = (const float*)d_in[9];
    const float* Wv    = (const float*)d_in[10];
    const float* bv    = (const float*)d_in[11];
    const float* rwb   = (const float*)d_in[12];
    const float* rrb   = (const float*)d_in[13];
    const float* rker  = (const float*)d_in[14];
    const float* rsb   = (const float*)d_in[15];
    const float* seg   = (const float*)d_in[16];
    const float* Wo    = (const float*)d_in[17];
    const float* bo    = (const float*)d_in[18];
    const float* lng   = (const float*)d_in[19];
    const float* lnb   = (const float*)d_in[20];

    float *gq, *gk, *gv, *gr, *gav, *gx;
    cudaGetSymbolAddress((void**)&gq,  g_q);
    cudaGetSymbolAddress((void**)&gk,  g_k);
    cudaGetSymbolAddress((void**)&gv,  g_v);
    cudaGetSymbolAddress((void**)&gr,  g_r);
    cudaGetSymbolAddress((void**)&gav, g_av);
    cudaGetSymbolAddress((void**)&gx,  g_x);

    cudaFuncSetAttribute(attn_kernel, cudaFuncAttributeMaxDynamicSharedMemorySize, ATTN_SMEM);

    detect_tt<<<1, 256>>>((const unsigned int*)ttm);

    tgemm_kernel<<<dim3(6, 32), 256>>>(query, Wq, nullptr, nullptr, gq,
                                       BATCH * SEQ, DMODEL, DMODEL, SCALE);
    tgemm_kernel<<<dim3(6, 32), 256>>>(key, Wk, bk, nullptr, gk,
                                       BATCH * SEQ, DMODEL, DMODEL, 1.f);
    tgemm_kernel<<<dim3(6, 32), 256>>>(value, Wv, bv, nullptr, gv,
                                       BATCH * SEQ, DMODEL, DMODEL, 1.f);
    tgemm_kernel<<<dim3(6, 16), 256>>>(pos, rker, nullptr, nullptr, gr,
                                       2 * SEQ, DMODEL, DMODEL, 1.f);

    attn_kernel<<<dim3(SEQ / TI, BATCH * NHEADS), 512, ATTN_SMEM>>>(
        gq, gk, gv, gr, ttm, amask, clsm, rwb, rrb, rsb, seg, gav);

    tgemm_kernel<<<dim3(6, 32), 256>>>(gav, Wo, bo, query, gx,
                                       BATCH * SEQ, DMODEL, DMODEL, 1.f);

    ln_kernel<<<BATCH * SEQ, 256>>>(gx, lng, lnb, (float*)d_out);
}

// round 6
// speedup vs baseline: 1.3271x; 1.0013x over previous
#include <cuda_runtime.h>
#include <cstdint>
#include <cstddef>

#define BATCH   4
#define SEQ     1024
#define DMODEL  768
#define NHEADS  12
#define HDIM    64
#define SCALE   0.125f

#define TI 16
#define TJ 64
#define RSROWS (TI + TJ - 1)
#define PAD 65

// tf32 GEMM tiles
#define GBM 128
#define GBN 128
#define GBK 32
#define ASTRIDE 36
#define BSTRIDE 132

__device__ float g_q [BATCH*SEQ*DMODEL];
__device__ float g_k [BATCH*SEQ*DMODEL];
__device__ float g_v [BATCH*SEQ*DMODEL];
__device__ float g_r [2*SEQ*DMODEL];
__device__ float g_av[BATCH*SEQ*DMODEL];
__device__ float g_x [BATCH*SEQ*DMODEL];
__device__ int   g_ttflag;

__global__ void detect_tt(const unsigned int* __restrict__ p) {
    __shared__ int sI, sF;
    if (threadIdx.x == 0) { sI = 1; sF = 1; }
    __syncthreads();
    int okI = 1, okF = 1;
    for (int i = threadIdx.x; i < 4096; i += 256) {
        unsigned v = p[i];
        if (v > 1u) okI = 0;
        if (v != 0u && v != 0x3F800000u) okF = 0;
    }
    if (!okI) atomicAnd(&sI, 0);
    if (!okF) atomicAnd(&sF, 0);
    __syncthreads();
    if (threadIdx.x == 0) g_ttflag = sI ? 0 : (sF ? 1 : 2);
}

__device__ __forceinline__ uint32_t f2tf32(float x) {
    uint32_t r;
    asm("cvt.rna.tf32.f32 %0, %1;" : "=r"(r) : "f"(x));
    return r;
}

__device__ __forceinline__ void mma_tf32(float* c, const uint32_t* a, const uint32_t* b) {
    asm volatile(
        "mma.sync.aligned.m16n8k8.row.col.f32.tf32.tf32.f32 "
        "{%0,%1,%2,%3}, {%4,%5,%6,%7}, {%8,%9}, {%0,%1,%2,%3};"
        : "+f"(c[0]), "+f"(c[1]), "+f"(c[2]), "+f"(c[3])
        : "r"(a[0]), "r"(a[1]), "r"(a[2]), "r"(a[3]), "r"(b[0]), "r"(b[1]));
}

// C = alpha*(A@B) (+bias) (+res), tf32 tensor-core path.
// A: MxK row-major, B: KxN row-major. M%128==0, N%128==0, K%32==0.
__global__ __launch_bounds__(256) void tgemm_kernel(
    const float* __restrict__ A, const float* __restrict__ B,
    const float* __restrict__ bias, const float* __restrict__ res,
    float* __restrict__ C, int M, int Nn, int K, float alpha)
{
    __shared__ uint32_t As[GBM][ASTRIDE];   // 128 x 36
    __shared__ uint32_t Bs[GBK][BSTRIDE];   // 32 x 132
    int tid = threadIdx.x;
    int warp = tid >> 5, lane = tid & 31;
    int wm = warp >> 2, wn = warp & 3;       // warps 2 (M) x 4 (N)
    int gid = lane >> 2, tig = lane & 3;     // groupID, thread-in-group
    int row0 = blockIdx.y * GBM, col0 = blockIdx.x * GBN;

    float acc[4][4][4];
#pragma unroll
    for (int mt = 0; mt < 4; mt++)
#pragma unroll
        for (int nt = 0; nt < 4; nt++)
#pragma unroll
            for (int e = 0; e < 4; e++) acc[mt][nt][e] = 0.f;

    for (int k0 = 0; k0 < K; k0 += GBK) {
        // stage A 128x32 and B 32x128 (1024 float4 each; 4 per thread each)
#pragma unroll
        for (int l = 0; l < 4; l++) {
            int idx = l * 256 + tid;
            int ra = idx >> 3, ca = (idx & 7) << 2;
            float4 va = *(const float4*)&A[(size_t)(row0 + ra) * K + k0 + ca];
            As[ra][ca + 0] = f2tf32(va.x);
            As[ra][ca + 1] = f2tf32(va.y);
            As[ra][ca + 2] = f2tf32(va.z);
            As[ra][ca + 3] = f2tf32(va.w);
            int rb = idx >> 5, cb = (idx & 31) << 2;
            float4 vb = *(const float4*)&B[(size_t)(k0 + rb) * Nn + col0 + cb];
            Bs[rb][cb + 0] = f2tf32(vb.x);
            Bs[rb][cb + 1] = f2tf32(vb.y);
            Bs[rb][cb + 2] = f2tf32(vb.z);
            Bs[rb][cb + 3] = f2tf32(vb.w);
        }
        __syncthreads();
#pragma unroll
        for (int kk = 0; kk < GBK; kk += 8) {
            uint32_t af[4][4];
#pragma unroll
            for (int mt = 0; mt < 4; mt++) {
                int r = wm * 64 + mt * 16 + gid;
                af[mt][0] = As[r    ][kk + tig];
                af[mt][1] = As[r + 8][kk + tig];
                af[mt][2] = As[r    ][kk + tig + 4];
                af[mt][3] = As[r + 8][kk + tig + 4];
            }
            uint32_t bf[4][2];
#pragma unroll
            for (int nt = 0; nt < 4; nt++) {
                int cn = wn * 32 + nt * 8 + gid;
                bf[nt][0] = Bs[kk + tig    ][cn];
                bf[nt][1] = Bs[kk + tig + 4][cn];
            }
#pragma unroll
            for (int mt = 0; mt < 4; mt++)
#pragma unroll
                for (int nt = 0; nt < 4; nt++)
                    mma_tf32(acc[mt][nt], af[mt], bf[nt]);
        }
        __syncthreads();
    }

    // epilogue
#pragma unroll
    for (int mt = 0; mt < 4; mt++) {
        int r = row0 + wm * 64 + mt * 16 + gid;
#pragma unroll
        for (int nt = 0; nt < 4; nt++) {
            int cn = col0 + wn * 32 + nt * 8 + tig * 2;
            float2 o0, o1;
            o0.x = alpha * acc[mt][nt][0]; o0.y = alpha * acc[mt][nt][1];
            o1.x = alpha * acc[mt][nt][2]; o1.y = alpha * acc[mt][nt][3];
            if (bias) {
                o0.x += bias[cn]; o0.y += bias[cn + 1];
                o1.x += bias[cn]; o1.y += bias[cn + 1];
            }
            if (res) {
                const float* rp0 = res + (size_t)r * Nn + cn;
                const float* rp1 = res + (size_t)(r + 8) * Nn + cn;
                o0.x += rp0[0]; o0.y += rp0[1];
                o1.x += rp1[0]; o1.y += rp1[1];
            }
            *(float2*)&C[(size_t)r * Nn + cn] = o0;
            *(float2*)&C[(size_t)(r + 8) * Nn + cn] = o1;
        }
    }
}

// Fused relative attention (R1-proven version: smem Q variants + smem P staging).
__global__ __launch_bounds__(512) void attn_kernel(
    const float* __restrict__ qh, const float* __restrict__ kh,
    const float* __restrict__ vh, const float* __restrict__ rh,
    const void*  __restrict__ ttp,
    const float* __restrict__ amask, const float* __restrict__ clsm,
    const float* __restrict__ rwb, const float* __restrict__ rrb,
    const float* __restrict__ rsb, const float* __restrict__ seg,
    float* __restrict__ av)
{
    extern __shared__ float sm[];
    float* Ks = sm;                       // TJ*PAD
    float* Vs = Ks + TJ * PAD;            // TJ*PAD
    float* Rs = Vs + TJ * PAD;            // RSROWS*PAD
    float* Qw = Rs + RSROWS * PAD;        // TI*PAD
    float* Qr = Qw + TI * PAD;            // TI*PAD
    float* Ps = Qr + TI * PAD;            // TI*TJ

    int tid = threadIdx.x;
    int w = tid >> 5, lane = tid & 31;
    int i0 = blockIdx.x * TI;
    int b = blockIdx.y / NHEADS, n = blockIdx.y % NHEADS;
    int i = i0 + w;
    int nh = n * HDIM;
    int flag = g_ttflag;

    const float* qrow = qh + ((size_t)(b * SEQ + i)) * DMODEL + nh;
    float q0 = qrow[lane], q1 = qrow[lane + 32];
    Qw[w * PAD + lane]      = q0 + __ldg(&rwb[nh + lane]) * SCALE;
    Qw[w * PAD + lane + 32] = q1 + __ldg(&rwb[nh + lane + 32]) * SCALE;
    Qr[w * PAD + lane]      = q0 + __ldg(&rrb[nh + lane]) * SCALE;
    Qr[w * PAD + lane + 32] = q1 + __ldg(&rrb[nh + lane + 32]) * SCALE;
    float qs0 = q0 + __ldg(&rsb[nh + lane]) * SCALE;
    float qs1 = q1 + __ldg(&rsb[nh + lane + 32]) * SCALE;
    float td = qs0 * __ldg(&seg[nh + lane]) + qs1 * __ldg(&seg[nh + lane + 32]);
    float ts = qs0 * __ldg(&seg[DMODEL + nh + lane]) + qs1 * __ldg(&seg[DMODEL + nh + lane + 32]);
#pragma unroll
    for (int o = 16; o; o >>= 1) {
        td += __shfl_xor_sync(0xffffffffu, td, o);
        ts += __shfl_xor_sync(0xffffffffu, ts, o);
    }

    float mrun = -1e30f, lrun = 0.f, acc0 = 0.f, acc1 = 0.f;
    const unsigned char* tt8  = (const unsigned char*)ttp;
    const int*           tt32 = (const int*)ttp;
    const float*         ttf  = (const float*)ttp;

    for (int jt = 0; jt < SEQ / TJ; jt++) {
        int j0 = jt * TJ;
#pragma unroll
        for (int l = 0; l < 2; l++) {
            int idx = tid + l * 512;
            int rrow = idx >> 4, c4 = (idx & 15) << 2;
            size_t gsrc = ((size_t)(b * SEQ + j0 + rrow)) * DMODEL + nh + c4;
            float4 kv = *(const float4*)&kh[gsrc];
            float4 vv = *(const float4*)&vh[gsrc];
            float* kd = &Ks[rrow * PAD + c4];
            kd[0] = kv.x; kd[1] = kv.y; kd[2] = kv.z; kd[3] = kv.w;
            float* vd = &Vs[rrow * PAD + c4];
            vd[0] = vv.x; vd[1] = vv.y; vd[2] = vv.z; vd[3] = vv.w;
        }
        int tb = SEQ + j0 - i0 - (TI - 1);
#pragma unroll
        for (int l = 0; l < 3; l++) {
            int idx = tid + l * 512;
            if (idx < RSROWS * 16) {
                int rrow = idx >> 4, c4 = (idx & 15) << 2;
                float4 rv = *(const float4*)&rh[((size_t)(tb + rrow)) * DMODEL + nh + c4];
                float* rd = &Rs[rrow * PAD + c4];
                rd[0] = rv.x; rd[1] = rv.y; rd[2] = rv.z; rd[3] = rv.w;
            }
        }
        __syncthreads();

        int c0 = lane, c1 = lane + 32;
        const float* kp0 = &Ks[c0 * PAD];
        const float* kp1 = &Ks[c1 * PAD];
        const float* rp0 = &Rs[(c0 - w + TI - 1) * PAD];
        const float* rp1 = &Rs[(c1 - w + TI - 1) * PAD];
        const float* qwp = &Qw[w * PAD];
        const float* qrp = &Qr[w * PAD];
        float s0 = 0.f, s1 = 0.f, p0 = 0.f, p1 = 0.f;
#pragma unroll
        for (int h = 0; h < HDIM; h++) {
            float qa = qwp[h], qb = qrp[h];
            s0 += qa * kp0[h]; s1 += qa * kp1[h];
            p0 += qb * rp0[h]; p1 += qb * rp1[h];
        }
        size_t cbase = (size_t)i * SEQ + j0;
        float cls0 = __ldg(&clsm[cbase + c0]);
        float cls1 = __ldg(&clsm[cbase + c1]);
        size_t tbase = ((size_t)b * SEQ + i) * SEQ + j0;
        bool m0, m1;
        if (flag == 2)      { m0 = tt8 [tbase + c0] != 0;   m1 = tt8 [tbase + c1] != 0; }
        else if (flag == 0) { m0 = tt32[tbase + c0] != 0;   m1 = tt32[tbase + c1] != 0; }
        else                { m0 = ttf [tbase + c0] != 0.f; m1 = ttf [tbase + c1] != 0.f; }
        float tt0 = m0 ? ts : td, tt1 = m1 ? ts : td;
        float am0 = __ldg(&amask[b * SEQ + j0 + c0]);
        float am1 = __ldg(&amask[b * SEQ + j0 + c1]);
        float sc0 = s0 + (p0 + tt0) * cls0 - 1000000.0f * (1.f - am0);
        float sc1 = s1 + (p1 + tt1) * cls1 - 1000000.0f * (1.f - am1);

        float mloc = fmaxf(sc0, sc1);
#pragma unroll
        for (int o = 16; o; o >>= 1) mloc = fmaxf(mloc, __shfl_xor_sync(0xffffffffu, mloc, o));
        float mnew = fmaxf(mrun, mloc);
        float corr = __expf(mrun - mnew);
        float e0 = __expf(sc0 - mnew), e1 = __expf(sc1 - mnew);
        float ls = e0 + e1;
#pragma unroll
        for (int o = 16; o; o >>= 1) ls += __shfl_xor_sync(0xffffffffu, ls, o);
        lrun = lrun * corr + ls;
        mrun = mnew;
        acc0 *= corr; acc1 *= corr;
        Ps[w * TJ + c0] = e0; Ps[w * TJ + c1] = e1;
        __syncwarp();
#pragma unroll 8
        for (int j = 0; j < TJ; j++) {
            float e = Ps[w * TJ + j];
            acc0 += e * Vs[j * PAD + lane];
            acc1 += e * Vs[j * PAD + lane + 32];
        }
        __syncthreads();
    }
    float inv = 1.f / lrun;
    float* od = av + ((size_t)(b * SEQ + i)) * DMODEL + nh;
    od[lane]      = acc0 * inv;
    od[lane + 32] = acc1 * inv;
}

__global__ __launch_bounds__(256) void ln_kernel(
    const float* __restrict__ x, const float* __restrict__ g,
    const float* __restrict__ bta, float* __restrict__ out)
{
    int row = blockIdx.x;
    int t = threadIdx.x;
    const float* xr = x + (size_t)row * DMODEL;
    float v0 = xr[t], v1 = xr[t + 256], v2 = xr[t + 512];
    __shared__ float red[32];
    int w = t >> 5, lane = t & 31;
    float s = v0 + v1 + v2;
#pragma unroll
    for (int o = 16; o; o >>= 1) s += __shfl_xor_sync(0xffffffffu, s, o);
    if (lane == 0) red[w] = s;
    __syncthreads();
    if (t < 32) {
        float r = (t < 8) ? red[t] : 0.f;
#pragma unroll
        for (int o = 4; o; o >>= 1) r += __shfl_xor_sync(0xffffffffu, r, o);
        if (t == 0) red[0] = r;
    }
    __syncthreads();
    float mu = red[0] * (1.f / DMODEL);
    float d0 = v0 - mu, d1 = v1 - mu, d2 = v2 - mu;
    float qv = d0 * d0 + d1 * d1 + d2 * d2;
#pragma unroll
    for (int o = 16; o; o >>= 1) qv += __shfl_xor_sync(0xffffffffu, qv, o);
    __syncthreads();
    if (lane == 0) red[w] = qv;
    __syncthreads();
    if (t < 32) {
        float r = (t < 8) ? red[t] : 0.f;
#pragma unroll
        for (int o = 4; o; o >>= 1) r += __shfl_xor_sync(0xffffffffu, r, o);
        if (t == 0) red[0] = r;
    }
    __syncthreads();
    float var = red[0] * (1.f / DMODEL);
    float rstd = rsqrtf(var + 1e-9f);
    size_t ob = (size_t)row * DMODEL;
    out[ob + t]       = d0 * rstd * g[t]       + bta[t];
    out[ob + t + 256] = d1 * rstd * g[t + 256] + bta[t + 256];
    out[ob + t + 512] = d2 * rstd * g[t + 512] + bta[t + 512];
}

static const int ATTN_SMEM = (2 * TJ * PAD + RSROWS * PAD + 2 * TI * PAD + TI * TJ) * (int)sizeof(float);

extern "C" void kernel_launch(void* const* d_in, const int* in_sizes, int n_in,
                              void* d_out, int out_size)
{
    (void)in_sizes; (void)n_in; (void)out_size;
    const float* query = (const float*)d_in[0];
    const float* key   = (const float*)d_in[1];
    const float* value = (const float*)d_in[2];
    const float* pos   = (const float*)d_in[3];
    const void*  ttm   = d_in[4];
    const float* amask = (const float*)d_in[5];
    const float* clsm  = (const float*)d_in[6];
    const float* Wq    = (const float*)d_in[7];
    const float* Wk    = (const float*)d_in[8];
    const float* bk    = (const float*)d_in[9];
    const float* Wv    = (const float*)d_in[10];
    const float* bv    = (const float*)d_in[11];
    const float* rwb   = (const float*)d_in[12];
    const float* rrb   = (const float*)d_in[13];
    const float* rker  = (const float*)d_in[14];
    const float* rsb   = (const float*)d_in[15];
    const float* seg   = (const float*)d_in[16];
    const float* Wo    = (const float*)d_in[17];
    const float* bo    = (const float*)d_in[18];
    const float* lng   = (const float*)d_in[19];
    const float* lnb   = (const float*)d_in[20];

    float *gq, *gk, *gv, *gr, *gav, *gx;
    cudaGetSymbolAddress((void**)&gq,  g_q);
    cudaGetSymbolAddress((void**)&gk,  g_k);
    cudaGetSymbolAddress((void**)&gv,  g_v);
    cudaGetSymbolAddress((void**)&gr,  g_r);
    cudaGetSymbolAddress((void**)&gav, g_av);
    cudaGetSymbolAddress((void**)&gx,  g_x);

    cudaFuncSetAttribute(attn_kernel, cudaFuncAttributeMaxDynamicSharedMemorySize, ATTN_SMEM);

    detect_tt<<<1, 256>>>((const unsigned int*)ttm);

    tgemm_kernel<<<dim3(6, 32), 256>>>(query, Wq, nullptr, nullptr, gq,
                                       BATCH * SEQ, DMODEL, DMODEL, SCALE);
    tgemm_kernel<<<dim3(6, 32), 256>>>(key, Wk, bk, nullptr, gk,
                                       BATCH * SEQ, DMODEL, DMODEL, 1.f);
    tgemm_kernel<<<dim3(6, 32), 256>>>(value, Wv, bv, nullptr, gv,
                                       BATCH * SEQ, DMODEL, DMODEL, 1.f);
    tgemm_kernel<<<dim3(6, 16), 256>>>(pos, rker, nullptr, nullptr, gr,
                                       2 * SEQ, DMODEL, DMODEL, 1.f);

    attn_kernel<<<dim3(SEQ / TI, BATCH * NHEADS), 512, ATTN_SMEM>>>(
        gq, gk, gv, gr, ttm, amask, clsm, rwb, rrb, rsb, seg, gav);

    tgemm_kernel<<<dim3(6, 32), 256>>>(gav, Wo, bo, query, gx,
                                       BATCH * SEQ, DMODEL, DMODEL, 1.f);

    ln_kernel<<<BATCH * SEQ, 256>>>(gx, lng, lnb, (float*)d_out);
}